// round 13
// baseline (speedup 1.0000x reference)
#include <cuda_runtime.h>
#include <math.h>

// VIN forward, B=128. W_v == 0 in this dataset => VI recursion is the identity;
// only q = conv(reward, W_q) at (sx,sy) matters, and
// logits = W_fc @ (W_q . r) = (W_fc @ W_q) . r = A . r.
// R13 (final): R12 + __frcp_rn softmax divide. Bench is at the launch floor;
// this is the converged kernel.
// Fallback (W_v != 0): dense path on global scratch (never taken here).

#define NQ 10
#define THREADS 384

#define SCR_PER 53248
__device__ float g_scr[128 * SCR_PER];

__global__ __launch_bounds__(THREADS, 1)
void vin_kernel(const float* __restrict__ input,    // [128,2,64,64]
                const int*   __restrict__ state_x,  // [128]
                const int*   __restrict__ state_y,  // [128]
                const int*   __restrict__ num_vi_p, // [1]
                const float* __restrict__ W_h,      // [150,2,3,3]
                const float* __restrict__ b_h,      // [150]
                const float* __restrict__ W_r,      // [150]
                const float* __restrict__ W_q,      // [10,9]
                const float* __restrict__ W_v,      // [10,9]
                const float* __restrict__ W_fc,     // [8,10]
                float* __restrict__ out, int out_half)
{
    __shared__ float patch[9][18];
    __shared__ int   pval[9];
    __shared__ float part[19][16];
    __shared__ float weffS[19];          // [0..17]=W_eff, [18]=b_eff
    __shared__ float Ash[8][9];          // A = W_fc @ W_q
    __shared__ float rsh[9];

    const int tid = threadIdx.x;
    const int b   = blockIdx.x;

    // ---- state loads first: head of the dependent chain ----
    int sx = 0, sy = 0;
    if (tid < 162) {
        sx = __ldg(state_x + b);
        sy = __ldg(state_y + b);
    }

    int nz = 0;

    // ---- W_eff partials: 19 outputs x 16 partials (threads 0..303) ----
    if (tid < 304) {
        int t = tid >> 4;                // 0..18
        int g = tid & 15;                // 0..15
        float s = 0.f;
        if (t < 18) {
            #pragma unroll 5
            for (int h = g; h < 150; h += 16) s = fmaf(W_r[h], W_h[h * 18 + t], s);
        } else {
            #pragma unroll 5
            for (int h = g; h < 150; h += 16) s = fmaf(W_r[h], b_h[h], s);
        }
        part[t][g] = s;
    } else if (tid < 376) {
        // ---- A = W_fc @ W_q : 72 entries, one per thread ----
        int t = tid - 304;               // 0..71
        int j = t / 9;
        int k = t % 9;
        float s = 0.f;
        #pragma unroll
        for (int ch = 0; ch < NQ; ch++)
            s = fmaf(W_fc[j * NQ + ch], W_q[ch * 9 + k], s);
        Ash[j][k] = s;
    }

    // ---- taps: one load per thread (162 threads), depends on state ----
    if (tid < 162) {
        int p   = tid / 18;
        int k   = tid % 18;
        int cin = k / 9;
        int tap = k % 9;
        int r  = sx - 1 + p / 3;
        int c  = sy - 1 + p % 3;
        int rr = r - 1 + tap / 3;
        int cc = c - 1 + tap % 3;
        bool pin = (r >= 0 && r < 64 && c >= 0 && c < 64);
        float v = 0.f;
        if (pin && rr >= 0 && rr < 64 && cc >= 0 && cc < 64)
            v = input[(size_t)b * 8192 + cin * 4096 + rr * 64 + cc];
        patch[p][k] = v;
        if (k == 0) pval[p] = pin ? 1 : 0;
    }

    // ---- W_v != 0 detection (strided, same epoch) ----
    for (int i = tid; i < 90; i += THREADS)
        if (W_v[i] != 0.0f) nz = 1;

    int flag = __syncthreads_or(nz);

    // ---- weff reduce, pairwise tree (depth 4) ----
    if (tid < 19) {
        const float* p = part[tid];
        float s01 = p[0] + p[1],   s23 = p[2] + p[3];
        float s45 = p[4] + p[5],   s67 = p[6] + p[7];
        float s89 = p[8] + p[9],   sab = p[10] + p[11];
        float scd = p[12] + p[13], sef = p[14] + p[15];
        weffS[tid] = (((s01 + s23) + (s45 + s67)) + ((s89 + sab) + (scd + sef)));
    }

    if (flag == 0) {
        // ================= FAST PATH (warp 0, all-SMEM tail) =================
        if (tid < 32) {
            __syncwarp();
            if (tid < 9) {
                float rv = 0.f;
                if (pval[tid]) {
                    rv = weffS[18];
                    #pragma unroll
                    for (int k = 0; k < 18; k++)
                        rv = fmaf(weffS[k], patch[tid][k], rv);
                }
                rsh[tid] = rv;
            }
            __syncwarp();
            if (tid < 8) {
                float l = 0.f;
                #pragma unroll
                for (int k = 0; k < 9; k++)
                    l = fmaf(Ash[tid][k], rsh[k], l);
                float m = l;
                #pragma unroll
                for (int o = 4; o > 0; o >>= 1)
                    m = fmaxf(m, __shfl_xor_sync(0xFF, m, o));
                float e = __expf(l - m);
                float den = e;
                #pragma unroll
                for (int o = 4; o > 0; o >>= 1)
                    den += __shfl_xor_sync(0xFF, den, o);
                float inv = __frcp_rn(den);
                out[b * 8 + tid]            = l;
                out[out_half + b * 8 + tid] = e * inv;
            }
        }
        return;
    }

    // ============ FALLBACK: dense VIN (correct, slow, never taken here) ============
    __syncthreads();

    float* rw = g_scr + (size_t)b * SCR_PER;
    float* v0 = rw + 4096;
    float* v1 = v0 + 4096;
    float* qr = v1 + 4096;

    for (int i = tid; i < 4096; i += THREADS) {
        int r = i >> 6, c = i & 63;
        float s = weffS[18];
        for (int cin = 0; cin < 2; cin++)
            for (int dy = 0; dy < 3; dy++) {
                int rr = r + dy - 1;
                if (rr < 0 || rr > 63) continue;
                for (int dx = 0; dx < 3; dx++) {
                    int cc = c + dx - 1;
                    if (cc < 0 || cc > 63) continue;
                    s = fmaf(weffS[cin * 9 + dy * 3 + dx],
                             input[(size_t)b * 8192 + cin * 4096 + rr * 64 + cc], s);
                }
            }
        rw[i] = s;
    }
    __syncthreads();

    for (int i = tid; i < 4096; i += THREADS) {
        int r = i >> 6, c = i & 63;
        float vmax = -1e30f;
        for (int ch = 0; ch < NQ; ch++) {
            float s = 0.f;
            for (int dy = 0; dy < 3; dy++) {
                int rr = r + dy - 1;
                if (rr < 0 || rr > 63) continue;
                for (int dx = 0; dx < 3; dx++) {
                    int cc = c + dx - 1;
                    if (cc < 0 || cc > 63) continue;
                    s = fmaf(W_q[ch * 9 + dy * 3 + dx], rw[rr * 64 + cc], s);
                }
            }
            qr[ch * 4096 + i] = s;
            vmax = fmaxf(vmax, s);
        }
        v0[i] = vmax;
    }
    __syncthreads();

    const int iters = num_vi_p[0] - 1;
    float* vc = v0;
    float* vn = v1;
    for (int it = 0; it < iters; it++) {
        for (int i = tid; i < 4096; i += THREADS) {
            int r = i >> 6, c = i & 63;
            float vmax = -1e30f;
            for (int ch = 0; ch < NQ; ch++) {
                float s = qr[ch * 4096 + i];
                for (int dy = 0; dy < 3; dy++) {
                    int rr = r + dy - 1;
                    if (rr < 0 || rr > 63) continue;
                    for (int dx = 0; dx < 3; dx++) {
                        int cc = c + dx - 1;
                        if (cc < 0 || cc > 63) continue;
                        s = fmaf(W_v[ch * 9 + dy * 3 + dx], vc[rr * 64 + cc], s);
                    }
                }
                vmax = fmaxf(vmax, s);
            }
            vn[i] = vmax;
        }
        __syncthreads();
        float* t = vc; vc = vn; vn = t;
    }

    if (tid == 0) {
        int sxx = state_x[b];
        int syy = state_y[b];
        float qxy[NQ];
        for (int ch = 0; ch < NQ; ch++) {
            float s = qr[ch * 4096 + sxx * 64 + syy];
            for (int dy = 0; dy < 3; dy++) {
                int rr = sxx + dy - 1;
                if (rr < 0 || rr > 63) continue;
                for (int dx = 0; dx < 3; dx++) {
                    int cc = syy + dx - 1;
                    if (cc < 0 || cc > 63) continue;
                    s = fmaf(W_v[ch * 9 + dy * 3 + dx], vc[rr * 64 + cc], s);
                }
            }
            qxy[ch] = s;
        }
        float l[8], m = -1e30f;
        for (int jj = 0; jj < 8; jj++) {
            float s = 0.f;
            for (int ch = 0; ch < NQ; ch++) s = fmaf(W_fc[jj * NQ + ch], qxy[ch], s);
            l[jj] = s;
            m = fmaxf(m, s);
        }
        float e[8], den = 0.f;
        for (int jj = 0; jj < 8; jj++) { e[jj] = expf(l[jj] - m); den += e[jj]; }
        float inv = 1.f / den;
        for (int jj = 0; jj < 8; jj++) {
            out[b * 8 + jj]            = l[jj];
            out[out_half + b * 8 + jj] = e[jj] * inv;
        }
    }
}

extern "C" void kernel_launch(void* const* d_in, const int* in_sizes, int n_in,
                              void* d_out, int out_size) {
    const float* input   = (const float*)d_in[0];
    const int*   state_x = (const int*)  d_in[1];
    const int*   state_y = (const int*)  d_in[2];
    const int*   num_vi  = (const int*)  d_in[3];
    const float* W_h     = (const float*)d_in[4];
    const float* b_h     = (const float*)d_in[5];
    const float* W_r     = (const float*)d_in[6];
    const float* W_q     = (const float*)d_in[7];
    const float* W_v     = (const float*)d_in[8];
    const float* W_fc    = (const float*)d_in[9];
    float* out = (float*)d_out;

    int B = in_sizes[1];
    vin_kernel<<<B, THREADS>>>(
        input, state_x, state_y, num_vi, W_h, b_h, W_r, W_q, W_v, W_fc,
        out, out_size / 2);
}

// round 14
// speedup vs baseline: 1.0333x; 1.0333x over previous
#include <cuda_runtime.h>
#include <math.h>

// VIN forward, B=128. W_v == 0 in this dataset => VI recursion is the identity;
// only q = conv(reward, W_q) at (sx,sy) matters.
// FINAL (= R10, session-best 8.672us): grid=128, 320 threads. state LDG issued
// first; W_eff split 19x16 (10 strided loads/thread); taps 1/thread; W_q/W_fc
// prefetch; one __syncthreads_or; all-SMEM 8-lane shfl softmax tail.
// Fallback (W_v != 0): dense path on global scratch (never taken here).

#define NQ 10
#define THREADS 320

#define SCR_PER 53248
__device__ float g_scr[128 * SCR_PER];

__global__ __launch_bounds__(THREADS, 1)
void vin_kernel(const float* __restrict__ input,    // [128,2,64,64]
                const int*   __restrict__ state_x,  // [128]
                const int*   __restrict__ state_y,  // [128]
                const int*   __restrict__ num_vi_p, // [1]
                const float* __restrict__ W_h,      // [150,2,3,3]
                const float* __restrict__ b_h,      // [150]
                const float* __restrict__ W_r,      // [150]
                const float* __restrict__ W_q,      // [10,9]
                const float* __restrict__ W_v,      // [10,9]
                const float* __restrict__ W_fc,     // [8,10]
                float* __restrict__ out, int out_half)
{
    __shared__ float patch[9][18];
    __shared__ int   pval[9];
    __shared__ float part[19][16];
    __shared__ float weffS[19];          // [0..17]=W_eff, [18]=b_eff
    __shared__ float wqS[90];
    __shared__ float wfcS[80];
    __shared__ float rsh[9];
    __shared__ float qsh[NQ];

    const int tid = threadIdx.x;
    const int b   = blockIdx.x;

    // ---- issue the state loads FIRST (head of the dependent chain) ----
    int sx = 0, sy = 0;
    if (tid < 162) {
        sx = __ldg(state_x + b);
        sy = __ldg(state_y + b);
    }

    int nz = 0;

    // ---- W_eff partials: 19 outputs x 16 partials (threads 0..303) ----
    // independent of state; these loads overlap the state-load epoch
    if (tid < 304) {
        int t = tid >> 4;                // 0..18
        int g = tid & 15;                // 0..15
        float s = 0.f;
        if (t < 18) {
            #pragma unroll 5
            for (int h = g; h < 150; h += 16) s = fmaf(W_r[h], W_h[h * 18 + t], s);
        } else {
            #pragma unroll 5
            for (int h = g; h < 150; h += 16) s = fmaf(W_r[h], b_h[h], s);
        }
        part[t][g] = s;
    } else {
        // threads 304..319: prefetch W_q / W_fc
        int t = tid - 304;               // 0..15
        #pragma unroll
        for (int i = t; i < 90; i += 16) wqS[i] = W_q[i];
        #pragma unroll
        for (int i = t; i < 80; i += 16) wfcS[i] = W_fc[i];
    }

    // ---- taps: one load per thread (162 threads), depends on state ----
    if (tid < 162) {
        int p   = tid / 18;
        int k   = tid % 18;
        int cin = k / 9;
        int tap = k % 9;
        int r  = sx - 1 + p / 3;
        int c  = sy - 1 + p % 3;
        int rr = r - 1 + tap / 3;
        int cc = c - 1 + tap % 3;
        bool pin = (r >= 0 && r < 64 && c >= 0 && c < 64);
        float v = 0.f;
        if (pin && rr >= 0 && rr < 64 && cc >= 0 && cc < 64)
            v = input[(size_t)b * 8192 + cin * 4096 + rr * 64 + cc];
        patch[p][k] = v;
        if (k == 0) pval[p] = pin ? 1 : 0;
    }

    // ---- W_v != 0 detection (strided, same epoch) ----
    for (int i = tid; i < 90; i += THREADS)
        if (W_v[i] != 0.0f) nz = 1;

    int flag = __syncthreads_or(nz);

    // ---- weff reduce (warp 0) ----
    if (tid < 19) {
        float s = 0.f;
        #pragma unroll
        for (int g = 0; g < 16; g++) s += part[tid][g];
        weffS[tid] = s;
    }

    if (flag == 0) {
        // ================= FAST PATH (warp 0, all-SMEM tail) =================
        if (tid < 32) {
            __syncwarp();
            if (tid < 9) {
                float rv = 0.f;
                if (pval[tid]) {
                    rv = weffS[18];
                    #pragma unroll
                    for (int k = 0; k < 18; k++)
                        rv = fmaf(weffS[k], patch[tid][k], rv);
                }
                rsh[tid] = rv;
            }
            __syncwarp();
            if (tid < NQ) {
                float s = 0.f;
                #pragma unroll
                for (int k = 0; k < 9; k++)
                    s = fmaf(wqS[tid * 9 + k], rsh[k], s);
                qsh[tid] = s;
            }
            __syncwarp();
            if (tid < 8) {
                float l = 0.f;
                #pragma unroll
                for (int ch = 0; ch < NQ; ch++)
                    l = fmaf(wfcS[tid * NQ + ch], qsh[ch], l);
                float m = l;
                #pragma unroll
                for (int o = 4; o > 0; o >>= 1)
                    m = fmaxf(m, __shfl_xor_sync(0xFF, m, o));
                float e = expf(l - m);
                float den = e;
                #pragma unroll
                for (int o = 4; o > 0; o >>= 1)
                    den += __shfl_xor_sync(0xFF, den, o);
                out[b * 8 + tid]            = l;
                out[out_half + b * 8 + tid] = e / den;
            }
        }
        return;
    }

    // ============ FALLBACK: dense VIN (correct, slow, never taken here) ============
    __syncthreads();

    float* rw = g_scr + (size_t)b * SCR_PER;
    float* v0 = rw + 4096;
    float* v1 = v0 + 4096;
    float* qr = v1 + 4096;

    for (int i = tid; i < 4096; i += THREADS) {
        int r = i >> 6, c = i & 63;
        float s = weffS[18];
        for (int cin = 0; cin < 2; cin++)
            for (int dy = 0; dy < 3; dy++) {
                int rr = r + dy - 1;
                if (rr < 0 || rr > 63) continue;
                for (int dx = 0; dx < 3; dx++) {
                    int cc = c + dx - 1;
                    if (cc < 0 || cc > 63) continue;
                    s = fmaf(weffS[cin * 9 + dy * 3 + dx],
                             input[(size_t)b * 8192 + cin * 4096 + rr * 64 + cc], s);
                }
            }
        rw[i] = s;
    }
    __syncthreads();

    for (int i = tid; i < 4096; i += THREADS) {
        int r = i >> 6, c = i & 63;
        float vmax = -1e30f;
        for (int ch = 0; ch < NQ; ch++) {
            float s = 0.f;
            for (int dy = 0; dy < 3; dy++) {
                int rr = r + dy - 1;
                if (rr < 0 || rr > 63) continue;
                for (int dx = 0; dx < 3; dx++) {
                    int cc = c + dx - 1;
                    if (cc < 0 || cc > 63) continue;
                    s = fmaf(wqS[ch * 9 + dy * 3 + dx], rw[rr * 64 + cc], s);
                }
            }
            qr[ch * 4096 + i] = s;
            vmax = fmaxf(vmax, s);
        }
        v0[i] = vmax;
    }
    __syncthreads();

    const int iters = num_vi_p[0] - 1;
    float* vc = v0;
    float* vn = v1;
    for (int it = 0; it < iters; it++) {
        for (int i = tid; i < 4096; i += THREADS) {
            int r = i >> 6, c = i & 63;
            float vmax = -1e30f;
            for (int ch = 0; ch < NQ; ch++) {
                float s = qr[ch * 4096 + i];
                for (int dy = 0; dy < 3; dy++) {
                    int rr = r + dy - 1;
                    if (rr < 0 || rr > 63) continue;
                    for (int dx = 0; dx < 3; dx++) {
                        int cc = c + dx - 1;
                        if (cc < 0 || cc > 63) continue;
                        s = fmaf(W_v[ch * 9 + dy * 3 + dx], vc[rr * 64 + cc], s);
                    }
                }
                vmax = fmaxf(vmax, s);
            }
            vn[i] = vmax;
        }
        __syncthreads();
        float* t = vc; vc = vn; vn = t;
    }

    if (tid == 0) {
        int sxx = state_x[b];
        int syy = state_y[b];
        float qxy[NQ];
        for (int ch = 0; ch < NQ; ch++) {
            float s = qr[ch * 4096 + sxx * 64 + syy];
            for (int dy = 0; dy < 3; dy++) {
                int rr = sxx + dy - 1;
                if (rr < 0 || rr > 63) continue;
                for (int dx = 0; dx < 3; dx++) {
                    int cc = syy + dx - 1;
                    if (cc < 0 || cc > 63) continue;
                    s = fmaf(W_v[ch * 9 + dy * 3 + dx], vc[rr * 64 + cc], s);
                }
            }
            qxy[ch] = s;
        }
        float l[8], m = -1e30f;
        for (int jj = 0; jj < 8; jj++) {
            float s = 0.f;
            for (int ch = 0; ch < NQ; ch++) s = fmaf(wfcS[jj * NQ + ch], qxy[ch], s);
            l[jj] = s;
            m = fmaxf(m, s);
        }
        float e[8], den = 0.f;
        for (int jj = 0; jj < 8; jj++) { e[jj] = expf(l[jj] - m); den += e[jj]; }
        float inv = 1.f / den;
        for (int jj = 0; jj < 8; jj++) {
            out[b * 8 + jj]            = l[jj];
            out[out_half + b * 8 + jj] = e[jj] * inv;
        }
    }
}

extern "C" void kernel_launch(void* const* d_in, const int* in_sizes, int n_in,
                              void* d_out, int out_size) {
    const float* input   = (const float*)d_in[0];
    const int*   state_x = (const int*)  d_in[1];
    const int*   state_y = (const int*)  d_in[2];
    const int*   num_vi  = (const int*)  d_in[3];
    const float* W_h     = (const float*)d_in[4];
    const float* b_h     = (const float*)d_in[5];
    const float* W_r     = (const float*)d_in[6];
    const float* W_q     = (const float*)d_in[7];
    const float* W_v     = (const float*)d_in[8];
    const float* W_fc    = (const float*)d_in[9];
    float* out = (float*)d_out;

    int B = in_sizes[1];
    vin_kernel<<<B, THREADS>>>(
        input, state_x, state_y, num_vi, W_h, b_h, W_r, W_q, W_v, W_fc,
        out, out_size / 2);
}